// round 11
// baseline (speedup 1.0000x reference)
#include <cuda_runtime.h>

#define NN   100000
#define EE   1600000
#define EAA  1000000
#define GG   512
#define F_INN 16
#define HH   32
#define SLOTS 96
#define SUB   24     // slots per sub-row (4 sub-rows)

// ---- scratch (device globals) ----
__device__ __align__(16) float g_deg[NN];          // dinv
__device__ __align__(16) float g_y  [NN * HH];     // layer-1 gather source (y1)
__device__ __align__(16) float g_y2 [NN * HH];     // layer-2 gather source (y2)
__device__ __align__(16) float g_h  [NN * HH];     // layer-2 output (edge head)
__device__ __align__(16) float g_u  [NN * HH];     // h @ Wbil
__device__ __align__(16) float g_pooled[GG * HH];
__device__ float g_cnt[GG];
__device__ __align__(16) int g_cnt4[NN * 4];       // 4 sub-counters per node
__device__ int   g_slot[NN * SLOTS];               // src ids, 4 sub-rows per dst

// ---------------- build kernels ----------------

__global__ void k_zero() {
    int i = blockIdx.x * blockDim.x + threadIdx.x;
    if (i < NN * 4)  g_cnt4[i] = 0;
    if (i < GG * HH) g_pooled[i] = 0.f;
    if (i < GG)      g_cnt[i] = 0.f;
}

// single pass: place src into dst's sub-row (4-way split counters: 4x less
// same-address atomic serialization)
__global__ void k_fillslot(const int* __restrict__ src, const int* __restrict__ dst) {
    int e = blockIdx.x * blockDim.x + threadIdx.x;
    if (e >= EE) return;
    int d = dst[e];
    int sub = e & 3;
    int slot = atomicAdd(&g_cnt4[d * 4 + sub], 1);
    g_slot[d * SLOTS + sub * SUB + slot] = src[e];
}

__global__ void k_dinv() {
    int i = blockIdx.x * blockDim.x + threadIdx.x;
    if (i >= NN) return;
    int4 c = reinterpret_cast<const int4*>(g_cnt4)[i];
    g_deg[i] = rsqrtf((float)(c.x + c.y + c.z + c.w) + 1.0f);
}

// ---------------- compute kernels ----------------

// y1 = (x @ W1) * dinv ; 4 threads per node ; W read via LDS.128
__global__ void k_mm1(const float* __restrict__ x, const float* __restrict__ W1) {
    __shared__ __align__(16) float sW[F_INN * HH];
    for (int i = threadIdx.x; i < F_INN * HH; i += blockDim.x) sW[i] = W1[i];
    __syncthreads();
    const float4* sW4 = reinterpret_cast<const float4*>(sW);
    int t = blockIdx.x * blockDim.x + threadIdx.x;
    int node = t >> 2, q = t & 3;
    if (node >= NN) return;
    float4 a0 = make_float4(0.f,0.f,0.f,0.f), a1 = make_float4(0.f,0.f,0.f,0.f);
    const float4* xr = reinterpret_cast<const float4*>(x + node * F_INN);
#pragma unroll
    for (int kk = 0; kk < F_INN / 4; kk++) {
        float4 xv = xr[kk];
        float xs[4] = {xv.x, xv.y, xv.z, xv.w};
#pragma unroll
        for (int p = 0; p < 4; p++) {
            int k = kk * 4 + p;
            float4 w0 = sW4[k * 8 + q * 2];       // cols q*8..q*8+3
            float4 w1 = sW4[k * 8 + q * 2 + 1];   // cols q*8+4..q*8+7
            a0.x = fmaf(xs[p], w0.x, a0.x); a0.y = fmaf(xs[p], w0.y, a0.y);
            a0.z = fmaf(xs[p], w0.z, a0.z); a0.w = fmaf(xs[p], w0.w, a0.w);
            a1.x = fmaf(xs[p], w1.x, a1.x); a1.y = fmaf(xs[p], w1.y, a1.y);
            a1.z = fmaf(xs[p], w1.z, a1.z); a1.w = fmaf(xs[p], w1.w, a1.w);
        }
    }
    float dv = g_deg[node];
    int o = node * 8 + q * 2;
    reinterpret_cast<float4*>(g_y)[o]     = make_float4(a0.x*dv, a0.y*dv, a0.z*dv, a0.w*dv);
    reinterpret_cast<float4*>(g_y)[o + 1] = make_float4(a1.x*dv, a1.y*dv, a1.z*dv, a1.w*dv);
}

// sum one slot segment at chunk c (unroll 2)
__device__ __forceinline__ float4 gather_seg(const float4* __restrict__ y4,
                                             int base, int m, int c, float4 acc) {
    int i = 0;
    for (; i + 2 <= m; i += 2) {
        int s0 = g_slot[base + i];
        int s1 = g_slot[base + i + 1];
        float4 v0 = y4[s0 * 8 + c];
        float4 v1 = y4[s1 * 8 + c];
        acc.x += v0.x + v1.x; acc.y += v0.y + v1.y;
        acc.z += v0.z + v1.z; acc.w += v0.w + v1.w;
    }
    if (i < m) {
        float4 v = y4[g_slot[base + i] * 8 + c];
        acc.x += v.x; acc.y += v.y; acc.z += v.z; acc.w += v.w;
    }
    return acc;
}

__device__ __forceinline__ float4 gather_node(const float4* __restrict__ y4,
                                              int node, int c, float4 acc) {
    int4 cnts = reinterpret_cast<const int4*>(g_cnt4)[node];
    int base = node * SLOTS;
    acc = gather_seg(y4, base,           cnts.x, c, acc);
    acc = gather_seg(y4, base + SUB,     cnts.y, c, acc);
    acc = gather_seg(y4, base + 2 * SUB, cnts.z, c, acc);
    acc = gather_seg(y4, base + 3 * SUB, cnts.w, c, acc);
    return acc;
}

// fused: slot gather of y1 + relu epilogue (smem) + @W2 matmul -> y2 (*dinv)
#define NODES_PER_BLK 32
#define HPAD 36
__global__ void k_gmm(const float* __restrict__ b1, const float* __restrict__ W2) {
    __shared__ __align__(16) float sW[HH * HH];
    __shared__ float sb[HH];
    __shared__ float sh[NODES_PER_BLK * HPAD];
    for (int i = threadIdx.x; i < HH * HH; i += blockDim.x) sW[i] = W2[i];
    if (threadIdx.x < HH) sb[threadIdx.x] = b1[threadIdx.x];
    __syncthreads();
    const float4* sW4 = reinterpret_cast<const float4*>(sW);

    int tid = threadIdx.x;
    int nl = tid >> 3, c = tid & 7;
    int node = blockIdx.x * NODES_PER_BLK + nl;
    bool ok = node < NN;

    if (ok) {
        const float4* y4 = reinterpret_cast<const float4*>(g_y);
        float4 acc = gather_node(y4, node, c, y4[node * 8 + c]);
        float dv = g_deg[node];
        float* hr = sh + nl * HPAD + c * 4;
        hr[0] = fmaxf(acc.x * dv + sb[c*4+0], 0.f);
        hr[1] = fmaxf(acc.y * dv + sb[c*4+1], 0.f);
        hr[2] = fmaxf(acc.z * dv + sb[c*4+2], 0.f);
        hr[3] = fmaxf(acc.w * dv + sb[c*4+3], 0.f);
    }
    __syncthreads();
    if (!ok) return;

    float4 a = make_float4(0.f, 0.f, 0.f, 0.f);
    const float* hrow = sh + nl * HPAD;
#pragma unroll
    for (int k = 0; k < HH; k++) {
        float hv = hrow[k];
        float4 w = sW4[k * 8 + c];          // cols c*4..c*4+3 (LDS.128)
        a.x = fmaf(hv, w.x, a.x); a.y = fmaf(hv, w.y, a.y);
        a.z = fmaf(hv, w.z, a.z); a.w = fmaf(hv, w.w, a.w);
    }
    float dv = g_deg[node];
    reinterpret_cast<float4*>(g_y2)[node * 8 + c] =
        make_float4(a.x * dv, a.y * dv, a.z * dv, a.w * dv);
}

// fused: slot gather of y2 + epilogue -> g_h, pooling, u = h2 @ Wbil -> g_u
__global__ void k_ghead(const float* __restrict__ b2, const float* __restrict__ Wbil,
                        const int* __restrict__ batch) {
    __shared__ __align__(16) float sW[HH * HH];
    __shared__ float sb[HH];
    __shared__ float sh[NODES_PER_BLK * HPAD];
    for (int i = threadIdx.x; i < HH * HH; i += blockDim.x) sW[i] = Wbil[i];
    if (threadIdx.x < HH) sb[threadIdx.x] = b2[threadIdx.x];
    __syncthreads();
    const float4* sW4 = reinterpret_cast<const float4*>(sW);

    int tid = threadIdx.x;
    int nl = tid >> 3, c = tid & 7;
    int node = blockIdx.x * NODES_PER_BLK + nl;
    bool ok = node < NN;

    if (ok) {
        const float4* y4 = reinterpret_cast<const float4*>(g_y2);
        float4 acc = gather_node(y4, node, c, y4[node * 8 + c]);
        float dv = g_deg[node];
        float4 h2;
        h2.x = acc.x * dv + sb[c*4+0];
        h2.y = acc.y * dv + sb[c*4+1];
        h2.z = acc.z * dv + sb[c*4+2];
        h2.w = acc.w * dv + sb[c*4+3];
        float* hr = sh + nl * HPAD + c * 4;
        hr[0] = h2.x; hr[1] = h2.y; hr[2] = h2.z; hr[3] = h2.w;
        reinterpret_cast<float4*>(g_h)[node * 8 + c] = h2;
        int g = batch[node];
        atomicAdd(reinterpret_cast<float4*>(g_pooled) + g * 8 + c, h2);
        if (c == 0) atomicAdd(&g_cnt[g], 1.0f);
    }
    __syncthreads();
    if (!ok) return;

    float4 a = make_float4(0.f, 0.f, 0.f, 0.f);
    const float* hrow = sh + nl * HPAD;
#pragma unroll
    for (int k = 0; k < HH; k++) {
        float hv = hrow[k];
        float4 w = sW4[k * 8 + c];
        a.x = fmaf(hv, w.x, a.x); a.y = fmaf(hv, w.y, a.y);
        a.z = fmaf(hv, w.z, a.z); a.w = fmaf(hv, w.w, a.w);
    }
    reinterpret_cast<float4*>(g_u)[node * 8 + c] = a;
}

// edge head (4 threads/edge, 2x float4 per operand) + fused reg head in last block
__global__ void k_edge(const int* __restrict__ asrc, const int* __restrict__ adst,
                       const float* __restrict__ bbil,
                       const float* __restrict__ Wr, const float* __restrict__ br,
                       float* __restrict__ out) {
    if (blockIdx.x == gridDim.x - 1) {
        for (int g = threadIdx.x; g < GG; g += 256) {
            float c = g_cnt[g];
            c = c < 1.f ? 1.f : c;
            float acc = 0.f;
#pragma unroll
            for (int h = 0; h < HH; h++) acc = fmaf(g_pooled[g * HH + h], Wr[h], acc);
            out[g] = acc / c + br[0];
        }
        return;
    }
    long t = (long)blockIdx.x * 256 + threadIdx.x;
    int e = (int)(t >> 2), lane = (int)(t & 3);
    if (e >= EAA) return;
    int s = asrc[e], d = adst[e];
    const float4* u4 = reinterpret_cast<const float4*>(g_u);
    const float4* h4 = reinterpret_cast<const float4*>(g_h);
    float4 a0 = u4[s * 8 + lane];
    float4 b0 = h4[d * 8 + lane];
    float4 a1 = u4[s * 8 + lane + 4];
    float4 b1 = h4[d * 8 + lane + 4];
    float p = a0.x*b0.x + a0.y*b0.y + a0.z*b0.z + a0.w*b0.w
            + a1.x*b1.x + a1.y*b1.y + a1.z*b1.z + a1.w*b1.w;
    p += __shfl_down_sync(0xffffffffu, p, 2, 4);
    p += __shfl_down_sync(0xffffffffu, p, 1, 4);
    if (lane == 0) out[GG + e] = p + bbil[0];
}

// ---------------- launch ----------------

extern "C" void kernel_launch(void* const* d_in, const int* in_sizes, int n_in,
                              void* d_out, int out_size) {
    const float* x    = (const float*)d_in[0];
    const int*   ei   = (const int*)  d_in[1];
    const int*   eia  = (const int*)  d_in[2];
    const int*   batch= (const int*)  d_in[3];
    const float* W1   = (const float*)d_in[4];
    const float* b1   = (const float*)d_in[5];
    const float* W2   = (const float*)d_in[6];
    const float* b2   = (const float*)d_in[7];
    const float* Wr   = (const float*)d_in[8];
    const float* br   = (const float*)d_in[9];
    const float* Wbil = (const float*)d_in[10];
    const float* bbil = (const float*)d_in[11];
    float* out = (float*)d_out;

    const int* src  = ei;
    const int* dst  = ei + EE;
    const int* asrc = eia;
    const int* adst = eia + EAA;

    const int B = 256;

    // one-pass slot build (4-way split counters)
    k_zero    <<<(NN * 4 + B - 1) / B, B>>>();
    k_fillslot<<<(EE + B - 1) / B, B>>>(src, dst);
    k_dinv    <<<(NN + B - 1) / B, B>>>();

    // layer 1 matmul, then fused gather+relu+layer2 matmul (y1 -> y2)
    k_mm1  <<<(NN * 4 + B - 1) / B, B>>>(x, W1);
    k_gmm  <<<(NN + NODES_PER_BLK - 1) / NODES_PER_BLK, B>>>(b1, W2);

    // fused gather(y2) + epilogue + pooling + bilinear precompute
    k_ghead<<<(NN + NODES_PER_BLK - 1) / NODES_PER_BLK, B>>>(b2, Wbil, batch);

    // edge head + fused reg head
    int edge_blocks = (int)(((long)EAA * 4 + B - 1) / B);
    k_edge <<<edge_blocks + 1, B>>>(asrc, adst, bbil, Wr, br, out);
}

// round 12
// speedup vs baseline: 1.1907x; 1.1907x over previous
#include <cuda_runtime.h>

#define NN   100000
#define EE   1600000
#define EAA  1000000
#define GG   512
#define F_INN 16
#define HH   32
#define SLOTS 96

#define FILL_BLOCKS ((EE + 255) / 256)        // 6250
#define MM1_BLOCKS  ((NN * 4 + 255) / 256)    // 1563

// ---- scratch (device globals) ----
__device__ __align__(16) float g_deg[NN];          // dinv
__device__ __align__(16) float g_y  [NN * HH];     // layer-1 gather source (y1)
__device__ __align__(16) float g_y2 [NN * HH];     // layer-2 gather source (y2)
__device__ __align__(16) float g_h  [NN * HH];     // layer-2 output (edge head)
__device__ __align__(16) float g_u  [NN * HH];     // h @ Wbil
__device__ __align__(16) float g_pooled[GG * HH];
__device__ float g_cnt[GG];
__device__ int   g_cnt_i[NN];                      // in-degree (no self loop)
__device__ int   g_slot[NN * SLOTS];               // src ids, fixed stride per dst

// ---------------- build ----------------

__global__ void k_zero() {
    int i = blockIdx.x * blockDim.x + threadIdx.x;
    if (i < NN)      g_cnt_i[i] = 0;
    if (i < GG * HH) g_pooled[i] = 0.f;
    if (i < GG)      g_cnt[i] = 0.f;
}

// fat kernel: blocks [0, FILL_BLOCKS) do the slot fill; the rest do
// xw = x @ W1 (UNSCALED) into g_y. The two tasks are independent and
// stress different pipes (L2 atomics vs FMA/L1), so they overlap.
__global__ void k_fused1(const int* __restrict__ src, const int* __restrict__ dst,
                         const float* __restrict__ x, const float* __restrict__ W1) {
    if (blockIdx.x < FILL_BLOCKS) {
        int e = blockIdx.x * 256 + threadIdx.x;
        if (e >= EE) return;
        int d = dst[e];
        int slot = atomicAdd(&g_cnt_i[d], 1);
        g_slot[d * SLOTS + slot] = src[e];
        return;
    }
    __shared__ float sW[F_INN * HH];
    for (int i = threadIdx.x; i < F_INN * HH; i += blockDim.x) sW[i] = W1[i];
    __syncthreads();
    int t = (blockIdx.x - FILL_BLOCKS) * 256 + threadIdx.x;
    int node = t >> 2, q = t & 3;
    if (node >= NN) return;
    float acc[8];
#pragma unroll
    for (int j = 0; j < 8; j++) acc[j] = 0.f;
    const float4* xr = reinterpret_cast<const float4*>(x + node * F_INN);
#pragma unroll
    for (int kk = 0; kk < F_INN / 4; kk++) {
        float4 xv = xr[kk];
        float xs[4] = {xv.x, xv.y, xv.z, xv.w};
#pragma unroll
        for (int p = 0; p < 4; p++) {
            int k = kk * 4 + p;
#pragma unroll
            for (int j = 0; j < 8; j++)
                acc[j] = fmaf(xs[p], sW[k * HH + q * 8 + j], acc[j]);
        }
    }
    int o = node * 8 + q * 2;
    reinterpret_cast<float4*>(g_y)[o]     = make_float4(acc[0], acc[1], acc[2], acc[3]);
    reinterpret_cast<float4*>(g_y)[o + 1] = make_float4(acc[4], acc[5], acc[6], acc[7]);
}

// dinv from counts + scale y in place: y *= dinv[node]
__global__ void k_scale() {
    int i = blockIdx.x * blockDim.x + threadIdx.x;
    if (i >= NN * 8) return;
    int node = i >> 3, c = i & 7;
    float dv = rsqrtf((float)g_cnt_i[node] + 1.0f);
    if (c == 0) g_deg[node] = dv;
    float4 v = reinterpret_cast<const float4*>(g_y)[i];
    reinterpret_cast<float4*>(g_y)[i] = make_float4(v.x*dv, v.y*dv, v.z*dv, v.w*dv);
}

// ---------------- compute kernels (round-10 proven) ----------------

// gather helper: sum y4 rows listed in g_slot[base..base+m) at chunk c, unroll 2
__device__ __forceinline__ float4 gather_rows(const float4* __restrict__ y4,
                                              int base, int m, int c, float4 acc) {
    int i = 0;
    for (; i + 2 <= m; i += 2) {
        int s0 = g_slot[base + i];
        int s1 = g_slot[base + i + 1];
        float4 v0 = y4[s0 * 8 + c];
        float4 v1 = y4[s1 * 8 + c];
        acc.x += v0.x + v1.x; acc.y += v0.y + v1.y;
        acc.z += v0.z + v1.z; acc.w += v0.w + v1.w;
    }
    if (i < m) {
        float4 v = y4[g_slot[base + i] * 8 + c];
        acc.x += v.x; acc.y += v.y; acc.z += v.z; acc.w += v.w;
    }
    return acc;
}

// fused: slot gather of y1 + relu epilogue (smem) + @W2 matmul -> y2 (*dinv)
#define NODES_PER_BLK 32
#define HPAD 36
__global__ void k_gmm(const float* __restrict__ b1, const float* __restrict__ W2) {
    __shared__ float sW[HH * HH];
    __shared__ float sb[HH];
    __shared__ float sh[NODES_PER_BLK * HPAD];
    for (int i = threadIdx.x; i < HH * HH; i += blockDim.x) sW[i] = W2[i];
    if (threadIdx.x < HH) sb[threadIdx.x] = b1[threadIdx.x];
    __syncthreads();

    int tid = threadIdx.x;
    int nl = tid >> 3, c = tid & 7;
    int node = blockIdx.x * NODES_PER_BLK + nl;
    bool ok = node < NN;

    if (ok) {
        int base = node * SLOTS;
        int m    = g_cnt_i[node];
        const float4* y4 = reinterpret_cast<const float4*>(g_y);
        float4 acc = gather_rows(y4, base, m, c, y4[node * 8 + c]);
        float dv = g_deg[node];
        float* hr = sh + nl * HPAD + c * 4;
        hr[0] = fmaxf(acc.x * dv + sb[c*4+0], 0.f);
        hr[1] = fmaxf(acc.y * dv + sb[c*4+1], 0.f);
        hr[2] = fmaxf(acc.z * dv + sb[c*4+2], 0.f);
        hr[3] = fmaxf(acc.w * dv + sb[c*4+3], 0.f);
    }
    __syncthreads();
    if (!ok) return;

    float a0 = 0.f, a1 = 0.f, a2 = 0.f, a3 = 0.f;
    const float* hrow = sh + nl * HPAD;
#pragma unroll
    for (int k = 0; k < HH; k++) {
        float hv = hrow[k];
        a0 = fmaf(hv, sW[k * HH + c * 4 + 0], a0);
        a1 = fmaf(hv, sW[k * HH + c * 4 + 1], a1);
        a2 = fmaf(hv, sW[k * HH + c * 4 + 2], a2);
        a3 = fmaf(hv, sW[k * HH + c * 4 + 3], a3);
    }
    float dv = g_deg[node];
    reinterpret_cast<float4*>(g_y2)[node * 8 + c] =
        make_float4(a0 * dv, a1 * dv, a2 * dv, a3 * dv);
}

// fused: slot gather of y2 + epilogue -> g_h, pooling, u = h2 @ Wbil -> g_u
__global__ void k_ghead(const float* __restrict__ b2, const float* __restrict__ Wbil,
                        const int* __restrict__ batch) {
    __shared__ float sW[HH * HH];
    __shared__ float sb[HH];
    __shared__ float sh[NODES_PER_BLK * HPAD];
    for (int i = threadIdx.x; i < HH * HH; i += blockDim.x) sW[i] = Wbil[i];
    if (threadIdx.x < HH) sb[threadIdx.x] = b2[threadIdx.x];
    __syncthreads();

    int tid = threadIdx.x;
    int nl = tid >> 3, c = tid & 7;
    int node = blockIdx.x * NODES_PER_BLK + nl;
    bool ok = node < NN;

    if (ok) {
        int base = node * SLOTS;
        int m    = g_cnt_i[node];
        const float4* y4 = reinterpret_cast<const float4*>(g_y2);
        float4 acc = gather_rows(y4, base, m, c, y4[node * 8 + c]);
        float dv = g_deg[node];
        float4 h2;
        h2.x = acc.x * dv + sb[c*4+0];
        h2.y = acc.y * dv + sb[c*4+1];
        h2.z = acc.z * dv + sb[c*4+2];
        h2.w = acc.w * dv + sb[c*4+3];
        float* hr = sh + nl * HPAD + c * 4;
        hr[0] = h2.x; hr[1] = h2.y; hr[2] = h2.z; hr[3] = h2.w;
        reinterpret_cast<float4*>(g_h)[node * 8 + c] = h2;
        int g = batch[node];
        atomicAdd(reinterpret_cast<float4*>(g_pooled) + g * 8 + c, h2);
        if (c == 0) atomicAdd(&g_cnt[g], 1.0f);
    }
    __syncthreads();
    if (!ok) return;

    float a0 = 0.f, a1 = 0.f, a2 = 0.f, a3 = 0.f;
    const float* hrow = sh + nl * HPAD;
#pragma unroll
    for (int k = 0; k < HH; k++) {
        float hv = hrow[k];
        a0 = fmaf(hv, sW[k * HH + c * 4 + 0], a0);
        a1 = fmaf(hv, sW[k * HH + c * 4 + 1], a1);
        a2 = fmaf(hv, sW[k * HH + c * 4 + 2], a2);
        a3 = fmaf(hv, sW[k * HH + c * 4 + 3], a3);
    }
    reinterpret_cast<float4*>(g_u)[node * 8 + c] = make_float4(a0, a1, a2, a3);
}

// edge head (4 threads/edge, 2x float4 per operand) + fused reg head in last block
__global__ void k_edge(const int* __restrict__ asrc, const int* __restrict__ adst,
                       const float* __restrict__ bbil,
                       const float* __restrict__ Wr, const float* __restrict__ br,
                       float* __restrict__ out) {
    if (blockIdx.x == gridDim.x - 1) {
        for (int g = threadIdx.x; g < GG; g += 256) {
            float c = g_cnt[g];
            c = c < 1.f ? 1.f : c;
            float acc = 0.f;
#pragma unroll
            for (int h = 0; h < HH; h++) acc = fmaf(g_pooled[g * HH + h], Wr[h], acc);
            out[g] = acc / c + br[0];
        }
        return;
    }
    long t = (long)blockIdx.x * 256 + threadIdx.x;
    int e = (int)(t >> 2), lane = (int)(t & 3);
    if (e >= EAA) return;
    int s = asrc[e], d = adst[e];
    const float4* u4 = reinterpret_cast<const float4*>(g_u);
    const float4* h4 = reinterpret_cast<const float4*>(g_h);
    float4 a0 = u4[s * 8 + lane];
    float4 b0 = h4[d * 8 + lane];
    float4 a1 = u4[s * 8 + lane + 4];
    float4 b1 = h4[d * 8 + lane + 4];
    float p = a0.x*b0.x + a0.y*b0.y + a0.z*b0.z + a0.w*b0.w
            + a1.x*b1.x + a1.y*b1.y + a1.z*b1.z + a1.w*b1.w;
    p += __shfl_down_sync(0xffffffffu, p, 2, 4);
    p += __shfl_down_sync(0xffffffffu, p, 1, 4);
    if (lane == 0) out[GG + e] = p + bbil[0];
}

// ---------------- launch ----------------

extern "C" void kernel_launch(void* const* d_in, const int* in_sizes, int n_in,
                              void* d_out, int out_size) {
    const float* x    = (const float*)d_in[0];
    const int*   ei   = (const int*)  d_in[1];
    const int*   eia  = (const int*)  d_in[2];
    const int*   batch= (const int*)  d_in[3];
    const float* W1   = (const float*)d_in[4];
    const float* b1   = (const float*)d_in[5];
    const float* W2   = (const float*)d_in[6];
    const float* b2   = (const float*)d_in[7];
    const float* Wr   = (const float*)d_in[8];
    const float* br   = (const float*)d_in[9];
    const float* Wbil = (const float*)d_in[10];
    const float* bbil = (const float*)d_in[11];
    float* out = (float*)d_out;

    const int* src  = ei;
    const int* dst  = ei + EE;
    const int* asrc = eia;
    const int* adst = eia + EAA;

    const int B = 256;

    // build + layer-1 matmul overlapped in one fat kernel
    k_zero  <<<(NN + B - 1) / B, B>>>();
    k_fused1<<<FILL_BLOCKS + MM1_BLOCKS, B>>>(src, dst, x, W1);
    k_scale <<<(NN * 8 + B - 1) / B, B>>>();

    // fused gather+relu+layer2 matmul (y1 -> y2)
    k_gmm  <<<(NN + NODES_PER_BLK - 1) / NODES_PER_BLK, B>>>(b1, W2);

    // fused gather(y2) + epilogue + pooling + bilinear precompute
    k_ghead<<<(NN + NODES_PER_BLK - 1) / NODES_PER_BLK, B>>>(b2, Wbil, batch);

    // edge head + fused reg head
    int edge_blocks = (int)(((long)EAA * 4 + B - 1) / B);
    k_edge <<<edge_blocks + 1, B>>>(asrc, adst, bbil, Wr, br, out);
}